// round 13
// baseline (speedup 1.0000x reference)
#include <cuda_runtime.h>
#include <cuda_fp16.h>
#include <cstdint>

#define F 64
#define X3F 192
#define AB 8
#define CHUNK 32
#define PAD_ATOM 0x3fffffff
#define NATOMS_CAP 25600
#define NEDGES_CAP 800000

// ---- device scratch (static: no allocs allowed) ----
__device__ __half g_x_h[(size_t)NATOMS_CAP * X3F];   // MLP output, fp16
__device__ __half g_mu_h[(size_t)NATOMS_CAP * X3F];  // mu copy, fp16
__device__ int    g_count[NATOMS_CAP];               // zeroed statically / re-zeroed each call
__device__ int    g_cursor[NATOMS_CAP];
__device__ int    g_off[NATOMS_CAP + 1];
__device__ int    g_perm[NEDGES_CAP];

// -------------------------------------------------------------------------
// Kernel 0: histogram (own launch -> high occupancy for the atomic pipe)
// -------------------------------------------------------------------------
__global__ __launch_bounds__(256)
void hist_kernel(const int* __restrict__ idx_i, int n_edges) {
    int base = (blockIdx.x * 256 + threadIdx.x) * 4;
    if (base + 3 < n_edges) {
        int4 v = *reinterpret_cast<const int4*>(idx_i + base);
        atomicAdd(&g_count[v.x], 1);
        atomicAdd(&g_count[v.y], 1);
        atomicAdd(&g_count[v.z], 1);
        atomicAdd(&g_count[v.w], 1);
    } else {
        for (int k = base; k < n_edges; k++) atomicAdd(&g_count[idx_i[k]], 1);
    }
}

// -------------------------------------------------------------------------
// Kernel 1: per-atom MLP (ILP-8) -> g_x_h fp16. (hist removed)
// -------------------------------------------------------------------------
__global__ __launch_bounds__(192, 2)
void mlp_kernel(const float* __restrict__ emb,
                const float* __restrict__ W1, const float* __restrict__ b1,
                const float* __restrict__ W2, const float* __restrict__ b2,
                int n_atoms) {
    __shared__ float emb_s[AB][F];
    __shared__ float h_s[AB][F];
    const int t = threadIdx.x;

    float w2col[F];
#pragma unroll
    for (int g = 0; g < F; g++) w2col[g] = W2[g * X3F + t];

    float w1col[F];
    float bias1 = 0.f;
    if (t < F) {
#pragma unroll
        for (int f = 0; f < F; f++) w1col[f] = W1[f * F + t];
        bias1 = b1[t];
    }
    const float bias2 = b2[t];

    const int nbatch = (n_atoms + AB - 1) / AB;
    for (int batch = blockIdx.x; batch < nbatch; batch += gridDim.x) {
        const int a0 = batch * AB;
        const int lim = min(AB, n_atoms - a0);
        {
            const float4* src = reinterpret_cast<const float4*>(emb + (size_t)a0 * F);
            float4* dst = reinterpret_cast<float4*>(&emb_s[0][0]);
            const int nv = lim * F / 4;
            for (int k = t; k < nv; k += 192) dst[k] = src[k];
        }
        __syncthreads();
        if (t < F) {
            float acc[AB];
#pragma unroll
            for (int a = 0; a < AB; a++) acc[a] = bias1;
#pragma unroll
            for (int f = 0; f < F; f += 4) {
#pragma unroll
                for (int a = 0; a < AB; a++) {
                    float4 e4 = *reinterpret_cast<const float4*>(&emb_s[a][f]);
                    acc[a] = fmaf(e4.x, w1col[f], acc[a]);
                    acc[a] = fmaf(e4.y, w1col[f + 1], acc[a]);
                    acc[a] = fmaf(e4.z, w1col[f + 2], acc[a]);
                    acc[a] = fmaf(e4.w, w1col[f + 3], acc[a]);
                }
            }
#pragma unroll
            for (int a = 0; a < AB; a++) {
                float v = acc[a];
                h_s[a][t] = v / (1.0f + __expf(-v));
            }
        }
        __syncthreads();
        {
            float acc[AB];
#pragma unroll
            for (int a = 0; a < AB; a++) acc[a] = bias2;
#pragma unroll
            for (int g = 0; g < F; g += 4) {
#pragma unroll
                for (int a = 0; a < AB; a++) {
                    float4 h4 = *reinterpret_cast<const float4*>(&h_s[a][g]);
                    acc[a] = fmaf(h4.x, w2col[g], acc[a]);
                    acc[a] = fmaf(h4.y, w2col[g + 1], acc[a]);
                    acc[a] = fmaf(h4.z, w2col[g + 2], acc[a]);
                    acc[a] = fmaf(h4.w, w2col[g + 3], acc[a]);
                }
            }
            for (int a = 0; a < lim; a++)
                g_x_h[(size_t)(a0 + a) * X3F + t] = __float2half(acc[a]);
        }
        __syncthreads();
    }
}

// -------------------------------------------------------------------------
// Kernel 2 (fused): block 0 = single-block scan; other blocks = output init
// -------------------------------------------------------------------------
__global__ __launch_bounds__(1024)
void scan_init_kernel(int n_atoms,
                      const float4* __restrict__ emb4, int nq4,
                      const float4* __restrict__ mu4, int nmu4,
                      float4* __restrict__ out4, int qinit_blocks) {
    const int tid = threadIdx.x;
    if (blockIdx.x == 0) {
        __shared__ int sh[1024];
        const int per = (n_atoms + 1023) / 1024;
        const int base = tid * per;
        int s = 0;
        for (int k = 0; k < per; k++) {
            int idx = base + k;
            if (idx < n_atoms) s += g_count[idx];
        }
        sh[tid] = s;
        __syncthreads();
        for (int d = 1; d < 1024; d <<= 1) {
            int v = 0;
            if (tid >= d) v = sh[tid - d];
            __syncthreads();
            if (tid >= d) sh[tid] += v;
            __syncthreads();
        }
        int run = sh[tid] - s;
        for (int k = 0; k < per; k++) {
            int idx = base + k;
            if (idx < n_atoms) {
                int c = g_count[idx];
                g_off[idx] = run;
                g_cursor[idx] = run;
                run += c;
            }
        }
        if (tid == 1023) g_off[n_atoms] = sh[1023];
    } else if (blockIdx.x <= qinit_blocks) {
        int i = (blockIdx.x - 1) * 1024 + tid;
        if (i < nq4) out4[i] = emb4[i];
    } else {
        int i = (blockIdx.x - 1 - qinit_blocks) * 1024 + tid;
        if (i < nmu4) {
            float4 v = mu4[i];
            out4[nq4 + i] = v;
            __half2* xh = reinterpret_cast<__half2*>(g_mu_h);
            xh[i * 2]     = __floats2half2_rn(v.x, v.y);
            xh[i * 2 + 1] = __floats2half2_rn(v.z, v.w);
        }
    }
}

// -------------------------------------------------------------------------
// Kernel 3 (fused): scatter perm (4 edges/thread) | zero g_count
// -------------------------------------------------------------------------
__global__ __launch_bounds__(256)
void util2_kernel(const int* __restrict__ idx_i, int n_edges,
                  int n_atoms, int scatter_blocks) {
    const int b = blockIdx.x;
    const int t = threadIdx.x;
    if (b < scatter_blocks) {
        int base = (b * 256 + t) * 4;
        if (base + 3 < n_edges) {
            int4 v = *reinterpret_cast<const int4*>(idx_i + base);
            int p0 = atomicAdd(&g_cursor[v.x], 1);
            int p1 = atomicAdd(&g_cursor[v.y], 1);
            int p2 = atomicAdd(&g_cursor[v.z], 1);
            int p3 = atomicAdd(&g_cursor[v.w], 1);
            g_perm[p0] = base;
            g_perm[p1] = base + 1;
            g_perm[p2] = base + 2;
            g_perm[p3] = base + 3;
        } else {
            for (int k = base; k < n_edges; k++) {
                int p = atomicAdd(&g_cursor[idx_i[k]], 1);
                g_perm[p] = k;
            }
        }
    } else {
        int i = (b - scatter_blocks) * 256 + t;
        if (i < n_atoms) g_count[i] = 0;
    }
}

// -------------------------------------------------------------------------
// Kernel 4: chunked segmented gather, 32 lanes/group, 2 channels/lane.
// 5 CTAs/SM (51-reg budget). Random x/mu gathers keep depth-1 prefetch;
// Wij loaded in-loop with __ldcs (streaming, evict-first).
// -------------------------------------------------------------------------
__device__ __forceinline__ void red2(float* p, float2 v) {
    asm volatile("red.global.add.v2.f32 [%0], {%1,%2};"
                 :: "l"(p), "f"(v.x), "f"(v.y)
                 : "memory");
}

struct GatherData {             // random-access part of one edge (6 regs)
    uint32_t xq, xr, xm;        // x_j segments (half2)
    uint32_t mj0, mj1, mj2;     // mu_j rows (half2)
};

__device__ __forceinline__ void load_gather(GatherData& d, int j, int c) {
    const uint32_t* xrow = reinterpret_cast<const uint32_t*>(g_x_h + (size_t)j * X3F);
    d.xq = xrow[c]; d.xr = xrow[32 + c]; d.xm = xrow[64 + c];
    const uint32_t* murow = reinterpret_cast<const uint32_t*>(g_mu_h + (size_t)j * X3F);
    d.mj0 = murow[c]; d.mj1 = murow[32 + c]; d.mj2 = murow[64 + c];
}

__device__ __forceinline__ float2 h2f2(uint32_t u) {
    return __half22float2(*reinterpret_cast<__half2*>(&u));
}

__device__ __forceinline__ void flush_atom2(int cur, int c,
                                            float2 q, float2 m0, float2 m1, float2 m2,
                                            float* q_out, float* mu_out) {
    red2(q_out + (size_t)cur * F + c * 2, q);
    float* mo = mu_out + (size_t)cur * X3F + c * 2;
    red2(mo, m0);
    red2(mo + F, m1);
    red2(mo + 2 * F, m2);
}

__global__ __launch_bounds__(256, 5)
void gather_kernel(const float* __restrict__ Wij,
                   const float* __restrict__ dir_ij,
                   const int* __restrict__ idx_i,
                   const int* __restrict__ idx_j,
                   float* __restrict__ q_out,
                   float* __restrict__ mu_out,
                   int n_edges, int n_atoms) {
    __shared__ int4   meta_i[8][CHUNK];    // {e, i, j, -}
    __shared__ float4 meta_f[8][CHUNK];    // {d0, d1, d2, -}

    const int t = threadIdx.x;
    const int w = t >> 5;                  // warp = group
    const int c = t & 31;                  // lane = 2-channel slot
    const int base = (blockIdx.x * 8 + w) * CHUNK;

    // metadata stage: lane c loads perm entry base+c (coalesced)
    {
        int p = base + c;
        int e = 0, i = PAD_ATOM, j = 0;
        float d0 = 0.f, d1 = 0.f, d2 = 0.f;
        if (p < n_edges) {
            e = g_perm[p];
            i = idx_i[e];
            j = idx_j[e];
            d0 = dir_ij[(size_t)e * 3 + 0];
            d1 = dir_ij[(size_t)e * 3 + 1];
            d2 = dir_ij[(size_t)e * 3 + 2];
        }
        meta_i[w][c] = make_int4(e, i, j, 0);
        meta_f[w][c] = make_float4(d0, d1, d2, 0.f);
    }
    __syncwarp();

    float2 q  = make_float2(0.f, 0.f);
    float2 m0 = q, m1 = q, m2 = q;
    int cur = -1;

    // prime pipeline (random gathers only)
    int4 mi = meta_i[w][0];
    GatherData d;
    load_gather(d, mi.z, c);

#pragma unroll 4
    for (int k = 0; k < CHUNK; k++) {
        int4 nmi = meta_i[w][(k + 1 < CHUNK) ? (k + 1) : (CHUNK - 1)];
        GatherData nd;
        load_gather(nd, nmi.z, c);

        // Wij: coalesced streaming load (evict-first)
        const float2* wp = reinterpret_cast<const float2*>(Wij + (size_t)mi.x * X3F);
        float2 wq = __ldcs(wp + c);
        float2 wr = __ldcs(wp + 32 + c);
        float2 wm = __ldcs(wp + 64 + c);

        if (mi.y != cur) {
            if (cur >= 0 && cur < n_atoms)
                flush_atom2(cur, c, q, m0, m1, m2, q_out, mu_out);
            cur = mi.y;
            q = m0 = m1 = m2 = make_float2(0.f, 0.f);
        }
        float4 mf = meta_f[w][k];

        float2 xq = h2f2(d.xq), xr = h2f2(d.xr), xm = h2f2(d.xm);
        float2 mj0 = h2f2(d.mj0), mj1 = h2f2(d.mj1), mj2 = h2f2(d.mj2);

        q.x = fmaf(wq.x, xq.x, q.x);
        q.y = fmaf(wq.y, xq.y, q.y);

        float2 a = make_float2(wr.x * xr.x, wr.y * xr.y);
        float2 b = make_float2(wm.x * xm.x, wm.y * xm.y);

        m0.x = fmaf(a.x, mf.x, fmaf(b.x, mj0.x, m0.x));
        m0.y = fmaf(a.y, mf.x, fmaf(b.y, mj0.y, m0.y));
        m1.x = fmaf(a.x, mf.y, fmaf(b.x, mj1.x, m1.x));
        m1.y = fmaf(a.y, mf.y, fmaf(b.y, mj1.y, m1.y));
        m2.x = fmaf(a.x, mf.z, fmaf(b.x, mj2.x, m2.x));
        m2.y = fmaf(a.y, mf.z, fmaf(b.y, mj2.y, m2.y));

        d = nd;
        mi = nmi;
    }
    if (cur >= 0 && cur < n_atoms)
        flush_atom2(cur, c, q, m0, m1, m2, q_out, mu_out);
}

// -------------------------------------------------------------------------
// Launch
// -------------------------------------------------------------------------
extern "C" void kernel_launch(void* const* d_in, const int* in_sizes, int n_in,
                              void* d_out, int out_size) {
    const float* emb   = (const float*)d_in[0];
    const float* mu    = (const float*)d_in[1];
    const float* Wij   = (const float*)d_in[2];
    const float* dir   = (const float*)d_in[3];
    const int*   idx_i = (const int*)d_in[4];
    const int*   idx_j = (const int*)d_in[5];
    const float* W1    = (const float*)d_in[6];
    const float* b1    = (const float*)d_in[7];
    const float* W2    = (const float*)d_in[8];
    const float* b2    = (const float*)d_in[9];

    const int n_atoms = in_sizes[0] / F;       // 25000
    const int n_edges = in_sizes[4];           // 800000

    float* q_out  = (float*)d_out;
    float* mu_out = (float*)d_out + (size_t)n_atoms * F;

    // 0) histogram (own launch, high occupancy)
    hist_kernel<<<(n_edges / 4 + 255) / 256, 256>>>(idx_i, n_edges);

    // 1) per-atom MLP -> g_x_h (fp16)
    mlp_kernel<<<296, 192>>>(emb, W1, b1, W2, b2, n_atoms);

    // 2) fused: scan (block 0) | output init + mu fp16 conv (other blocks)
    {
        int nq4  = n_atoms * F / 4;
        int nmu4 = n_atoms * X3F / 4;
        int qinit_blocks  = (nq4 + 1023) / 1024;
        int muinit_blocks = (nmu4 + 1023) / 1024;
        scan_init_kernel<<<1 + qinit_blocks + muinit_blocks, 1024>>>(
            n_atoms, (const float4*)emb, nq4, (const float4*)mu, nmu4,
            (float4*)d_out, qinit_blocks);
    }

    // 3) fused: scatter perm | zero g_count (for next call)
    {
        int scatter_blocks = (n_edges / 4 + 255) / 256;
        int zero_blocks = (n_atoms + 255) / 256;
        util2_kernel<<<scatter_blocks + zero_blocks, 256>>>(
            idx_i, n_edges, n_atoms, scatter_blocks);
    }

    // 4) high-occupancy pipelined gather (32 lanes/edge, CHUNK=32, 5 CTA/SM)
    {
        int edges_per_block = 8 * CHUNK;   // 8 warps x 32 edges
        int blocks = (n_edges + edges_per_block - 1) / edges_per_block;
        gather_kernel<<<blocks, 256>>>(Wij, dir, idx_i, idx_j,
                                       q_out, mu_out, n_edges, n_atoms);
    }
}

// round 14
// speedup vs baseline: 1.0616x; 1.0616x over previous
#include <cuda_runtime.h>
#include <cuda_fp16.h>
#include <cstdint>

#define F 64
#define X3F 192
#define AB 8
#define CHUNK 32
#define PAD_ATOM 0x3fffffff
#define NATOMS_CAP 25600
#define NEDGES_CAP 800000

// ---- device scratch (static: no allocs allowed) ----
__device__ __half g_x_h[(size_t)NATOMS_CAP * X3F];   // MLP output, fp16
__device__ __half g_mu_h[(size_t)NATOMS_CAP * X3F];  // mu copy, fp16
__device__ int    g_count[NATOMS_CAP];               // zeroed statically / re-zeroed each call
__device__ int    g_cursor[NATOMS_CAP];
__device__ int    g_off[NATOMS_CAP + 1];
__device__ int    g_perm[NEDGES_CAP];

// -------------------------------------------------------------------------
// Kernel 0: histogram (own launch -> high occupancy for the atomic pipe)
// -------------------------------------------------------------------------
__global__ __launch_bounds__(256)
void hist_kernel(const int* __restrict__ idx_i, int n_edges) {
    int base = (blockIdx.x * 256 + threadIdx.x) * 4;
    if (base + 3 < n_edges) {
        int4 v = *reinterpret_cast<const int4*>(idx_i + base);
        atomicAdd(&g_count[v.x], 1);
        atomicAdd(&g_count[v.y], 1);
        atomicAdd(&g_count[v.z], 1);
        atomicAdd(&g_count[v.w], 1);
    } else {
        for (int k = base; k < n_edges; k++) atomicAdd(&g_count[idx_i[k]], 1);
    }
}

// -------------------------------------------------------------------------
// Kernel 1: per-atom MLP (ILP-8) -> g_x_h fp16.
// -------------------------------------------------------------------------
__global__ __launch_bounds__(192, 2)
void mlp_kernel(const float* __restrict__ emb,
                const float* __restrict__ W1, const float* __restrict__ b1,
                const float* __restrict__ W2, const float* __restrict__ b2,
                int n_atoms) {
    __shared__ float emb_s[AB][F];
    __shared__ float h_s[AB][F];
    const int t = threadIdx.x;

    float w2col[F];
#pragma unroll
    for (int g = 0; g < F; g++) w2col[g] = W2[g * X3F + t];

    float w1col[F];
    float bias1 = 0.f;
    if (t < F) {
#pragma unroll
        for (int f = 0; f < F; f++) w1col[f] = W1[f * F + t];
        bias1 = b1[t];
    }
    const float bias2 = b2[t];

    const int nbatch = (n_atoms + AB - 1) / AB;
    for (int batch = blockIdx.x; batch < nbatch; batch += gridDim.x) {
        const int a0 = batch * AB;
        const int lim = min(AB, n_atoms - a0);
        {
            const float4* src = reinterpret_cast<const float4*>(emb + (size_t)a0 * F);
            float4* dst = reinterpret_cast<float4*>(&emb_s[0][0]);
            const int nv = lim * F / 4;
            for (int k = t; k < nv; k += 192) dst[k] = src[k];
        }
        __syncthreads();
        if (t < F) {
            float acc[AB];
#pragma unroll
            for (int a = 0; a < AB; a++) acc[a] = bias1;
#pragma unroll
            for (int f = 0; f < F; f += 4) {
#pragma unroll
                for (int a = 0; a < AB; a++) {
                    float4 e4 = *reinterpret_cast<const float4*>(&emb_s[a][f]);
                    acc[a] = fmaf(e4.x, w1col[f], acc[a]);
                    acc[a] = fmaf(e4.y, w1col[f + 1], acc[a]);
                    acc[a] = fmaf(e4.z, w1col[f + 2], acc[a]);
                    acc[a] = fmaf(e4.w, w1col[f + 3], acc[a]);
                }
            }
#pragma unroll
            for (int a = 0; a < AB; a++) {
                float v = acc[a];
                h_s[a][t] = v / (1.0f + __expf(-v));
            }
        }
        __syncthreads();
        {
            float acc[AB];
#pragma unroll
            for (int a = 0; a < AB; a++) acc[a] = bias2;
#pragma unroll
            for (int g = 0; g < F; g += 4) {
#pragma unroll
                for (int a = 0; a < AB; a++) {
                    float4 h4 = *reinterpret_cast<const float4*>(&h_s[a][g]);
                    acc[a] = fmaf(h4.x, w2col[g], acc[a]);
                    acc[a] = fmaf(h4.y, w2col[g + 1], acc[a]);
                    acc[a] = fmaf(h4.z, w2col[g + 2], acc[a]);
                    acc[a] = fmaf(h4.w, w2col[g + 3], acc[a]);
                }
            }
            for (int a = 0; a < lim; a++)
                g_x_h[(size_t)(a0 + a) * X3F + t] = __float2half(acc[a]);
        }
        __syncthreads();
    }
}

// -------------------------------------------------------------------------
// Kernel 2 (fused): block 0 = single-block scan; other blocks = output init
// -------------------------------------------------------------------------
__global__ __launch_bounds__(1024)
void scan_init_kernel(int n_atoms,
                      const float4* __restrict__ emb4, int nq4,
                      const float4* __restrict__ mu4, int nmu4,
                      float4* __restrict__ out4, int qinit_blocks) {
    const int tid = threadIdx.x;
    if (blockIdx.x == 0) {
        __shared__ int sh[1024];
        const int per = (n_atoms + 1023) / 1024;
        const int base = tid * per;
        int s = 0;
        for (int k = 0; k < per; k++) {
            int idx = base + k;
            if (idx < n_atoms) s += g_count[idx];
        }
        sh[tid] = s;
        __syncthreads();
        for (int d = 1; d < 1024; d <<= 1) {
            int v = 0;
            if (tid >= d) v = sh[tid - d];
            __syncthreads();
            if (tid >= d) sh[tid] += v;
            __syncthreads();
        }
        int run = sh[tid] - s;
        for (int k = 0; k < per; k++) {
            int idx = base + k;
            if (idx < n_atoms) {
                int c = g_count[idx];
                g_off[idx] = run;
                g_cursor[idx] = run;
                run += c;
            }
        }
        if (tid == 1023) g_off[n_atoms] = sh[1023];
    } else if (blockIdx.x <= qinit_blocks) {
        int i = (blockIdx.x - 1) * 1024 + tid;
        if (i < nq4) out4[i] = emb4[i];
    } else {
        int i = (blockIdx.x - 1 - qinit_blocks) * 1024 + tid;
        if (i < nmu4) {
            float4 v = mu4[i];
            out4[nq4 + i] = v;
            __half2* xh = reinterpret_cast<__half2*>(g_mu_h);
            xh[i * 2]     = __floats2half2_rn(v.x, v.y);
            xh[i * 2 + 1] = __floats2half2_rn(v.z, v.w);
        }
    }
}

// -------------------------------------------------------------------------
// Kernel 3 (fused): scatter perm (4 edges/thread) | zero g_count
// -------------------------------------------------------------------------
__global__ __launch_bounds__(256)
void util2_kernel(const int* __restrict__ idx_i, int n_edges,
                  int n_atoms, int scatter_blocks) {
    const int b = blockIdx.x;
    const int t = threadIdx.x;
    if (b < scatter_blocks) {
        int base = (b * 256 + t) * 4;
        if (base + 3 < n_edges) {
            int4 v = *reinterpret_cast<const int4*>(idx_i + base);
            int p0 = atomicAdd(&g_cursor[v.x], 1);
            int p1 = atomicAdd(&g_cursor[v.y], 1);
            int p2 = atomicAdd(&g_cursor[v.z], 1);
            int p3 = atomicAdd(&g_cursor[v.w], 1);
            g_perm[p0] = base;
            g_perm[p1] = base + 1;
            g_perm[p2] = base + 2;
            g_perm[p3] = base + 3;
        } else {
            for (int k = base; k < n_edges; k++) {
                int p = atomicAdd(&g_cursor[idx_i[k]], 1);
                g_perm[p] = k;
            }
        }
    } else {
        int i = (b - scatter_blocks) * 256 + t;
        if (i < n_atoms) g_count[i] = 0;
    }
}

// -------------------------------------------------------------------------
// Kernel 4: chunked segmented gather — EXACT R12 configuration (4 CTAs/SM,
// 64 regs, no spills, measured 135.4us). Random x/mu gathers keep depth-1
// prefetch; Wij loaded in-loop with __ldcs (streaming, evict-first).
// -------------------------------------------------------------------------
__device__ __forceinline__ void red2(float* p, float2 v) {
    asm volatile("red.global.add.v2.f32 [%0], {%1,%2};"
                 :: "l"(p), "f"(v.x), "f"(v.y)
                 : "memory");
}

struct GatherData {             // random-access part of one edge (6 regs)
    uint32_t xq, xr, xm;        // x_j segments (half2)
    uint32_t mj0, mj1, mj2;     // mu_j rows (half2)
};

__device__ __forceinline__ void load_gather(GatherData& d, int j, int c) {
    const uint32_t* xrow = reinterpret_cast<const uint32_t*>(g_x_h + (size_t)j * X3F);
    d.xq = xrow[c]; d.xr = xrow[32 + c]; d.xm = xrow[64 + c];
    const uint32_t* murow = reinterpret_cast<const uint32_t*>(g_mu_h + (size_t)j * X3F);
    d.mj0 = murow[c]; d.mj1 = murow[32 + c]; d.mj2 = murow[64 + c];
}

__device__ __forceinline__ float2 h2f2(uint32_t u) {
    return __half22float2(*reinterpret_cast<__half2*>(&u));
}

__device__ __forceinline__ void flush_atom2(int cur, int c,
                                            float2 q, float2 m0, float2 m1, float2 m2,
                                            float* q_out, float* mu_out) {
    red2(q_out + (size_t)cur * F + c * 2, q);
    float* mo = mu_out + (size_t)cur * X3F + c * 2;
    red2(mo, m0);
    red2(mo + F, m1);
    red2(mo + 2 * F, m2);
}

__global__ __launch_bounds__(256, 4)
void gather_kernel(const float* __restrict__ Wij,
                   const float* __restrict__ dir_ij,
                   const int* __restrict__ idx_i,
                   const int* __restrict__ idx_j,
                   float* __restrict__ q_out,
                   float* __restrict__ mu_out,
                   int n_edges, int n_atoms) {
    __shared__ int4   meta_i[8][CHUNK];    // {e, i, j, -}
    __shared__ float4 meta_f[8][CHUNK];    // {d0, d1, d2, -}

    const int t = threadIdx.x;
    const int w = t >> 5;                  // warp = group
    const int c = t & 31;                  // lane = 2-channel slot
    const int base = (blockIdx.x * 8 + w) * CHUNK;

    // metadata stage: lane c loads perm entry base+c (coalesced)
    {
        int p = base + c;
        int e = 0, i = PAD_ATOM, j = 0;
        float d0 = 0.f, d1 = 0.f, d2 = 0.f;
        if (p < n_edges) {
            e = g_perm[p];
            i = idx_i[e];
            j = idx_j[e];
            d0 = dir_ij[(size_t)e * 3 + 0];
            d1 = dir_ij[(size_t)e * 3 + 1];
            d2 = dir_ij[(size_t)e * 3 + 2];
        }
        meta_i[w][c] = make_int4(e, i, j, 0);
        meta_f[w][c] = make_float4(d0, d1, d2, 0.f);
    }
    __syncwarp();

    float2 q  = make_float2(0.f, 0.f);
    float2 m0 = q, m1 = q, m2 = q;
    int cur = -1;

    // prime pipeline (random gathers only)
    int4 mi = meta_i[w][0];
    GatherData d;
    load_gather(d, mi.z, c);

#pragma unroll 4
    for (int k = 0; k < CHUNK; k++) {
        int4 nmi = meta_i[w][(k + 1 < CHUNK) ? (k + 1) : (CHUNK - 1)];
        GatherData nd;
        load_gather(nd, nmi.z, c);

        // Wij: coalesced streaming load (evict-first)
        const float2* wp = reinterpret_cast<const float2*>(Wij + (size_t)mi.x * X3F);
        float2 wq = __ldcs(wp + c);
        float2 wr = __ldcs(wp + 32 + c);
        float2 wm = __ldcs(wp + 64 + c);

        if (mi.y != cur) {
            if (cur >= 0 && cur < n_atoms)
                flush_atom2(cur, c, q, m0, m1, m2, q_out, mu_out);
            cur = mi.y;
            q = m0 = m1 = m2 = make_float2(0.f, 0.f);
        }
        float4 mf = meta_f[w][k];

        float2 xq = h2f2(d.xq), xr = h2f2(d.xr), xm = h2f2(d.xm);
        float2 mj0 = h2f2(d.mj0), mj1 = h2f2(d.mj1), mj2 = h2f2(d.mj2);

        q.x = fmaf(wq.x, xq.x, q.x);
        q.y = fmaf(wq.y, xq.y, q.y);

        float2 a = make_float2(wr.x * xr.x, wr.y * xr.y);
        float2 b = make_float2(wm.x * xm.x, wm.y * xm.y);

        m0.x = fmaf(a.x, mf.x, fmaf(b.x, mj0.x, m0.x));
        m0.y = fmaf(a.y, mf.x, fmaf(b.y, mj0.y, m0.y));
        m1.x = fmaf(a.x, mf.y, fmaf(b.x, mj1.x, m1.x));
        m1.y = fmaf(a.y, mf.y, fmaf(b.y, mj1.y, m1.y));
        m2.x = fmaf(a.x, mf.z, fmaf(b.x, mj2.x, m2.x));
        m2.y = fmaf(a.y, mf.z, fmaf(b.y, mj2.y, m2.y));

        d = nd;
        mi = nmi;
    }
    if (cur >= 0 && cur < n_atoms)
        flush_atom2(cur, c, q, m0, m1, m2, q_out, mu_out);
}

// -------------------------------------------------------------------------
// Launch
// -------------------------------------------------------------------------
extern "C" void kernel_launch(void* const* d_in, const int* in_sizes, int n_in,
                              void* d_out, int out_size) {
    const float* emb   = (const float*)d_in[0];
    const float* mu    = (const float*)d_in[1];
    const float* Wij   = (const float*)d_in[2];
    const float* dir   = (const float*)d_in[3];
    const int*   idx_i = (const int*)d_in[4];
    const int*   idx_j = (const int*)d_in[5];
    const float* W1    = (const float*)d_in[6];
    const float* b1    = (const float*)d_in[7];
    const float* W2    = (const float*)d_in[8];
    const float* b2    = (const float*)d_in[9];

    const int n_atoms = in_sizes[0] / F;       // 25000
    const int n_edges = in_sizes[4];           // 800000

    float* q_out  = (float*)d_out;
    float* mu_out = (float*)d_out + (size_t)n_atoms * F;

    // 0) histogram (own launch, high occupancy)
    hist_kernel<<<(n_edges / 4 + 255) / 256, 256>>>(idx_i, n_edges);

    // 1) per-atom MLP -> g_x_h (fp16)
    mlp_kernel<<<296, 192>>>(emb, W1, b1, W2, b2, n_atoms);

    // 2) fused: scan (block 0) | output init + mu fp16 conv (other blocks)
    {
        int nq4  = n_atoms * F / 4;
        int nmu4 = n_atoms * X3F / 4;
        int qinit_blocks  = (nq4 + 1023) / 1024;
        int muinit_blocks = (nmu4 + 1023) / 1024;
        scan_init_kernel<<<1 + qinit_blocks + muinit_blocks, 1024>>>(
            n_atoms, (const float4*)emb, nq4, (const float4*)mu, nmu4,
            (float4*)d_out, qinit_blocks);
    }

    // 3) fused: scatter perm | zero g_count (for next call)
    {
        int scatter_blocks = (n_edges / 4 + 255) / 256;
        int zero_blocks = (n_atoms + 255) / 256;
        util2_kernel<<<scatter_blocks + zero_blocks, 256>>>(
            idx_i, n_edges, n_atoms, scatter_blocks);
    }

    // 4) gather (R12-proven config: 4 CTA/SM, no spills)
    {
        int edges_per_block = 8 * CHUNK;   // 8 warps x 32 edges
        int blocks = (n_edges + edges_per_block - 1) / edges_per_block;
        gather_kernel<<<blocks, 256>>>(Wij, dir, idx_i, idx_j,
                                       q_out, mu_out, n_edges, n_atoms);
    }
}

// round 15
// speedup vs baseline: 1.0991x; 1.0354x over previous
#include <cuda_runtime.h>
#include <cuda_fp16.h>
#include <cstdint>

#define F 64
#define X3F 192
#define AB 8
#define CHUNK 32
#define PAD_ATOM 0x3fffffff
#define NATOMS_CAP 25600
#define NEDGES_CAP 800000

// ---- device scratch (static: no allocs allowed) ----
__device__ __half g_x_h[(size_t)NATOMS_CAP * X3F];   // MLP output, fp16
__device__ __half g_mu_h[(size_t)NATOMS_CAP * X3F];  // mu copy, fp16
__device__ int    g_count[NATOMS_CAP];               // zeroed statically / re-zeroed each call
__device__ int    g_cursor[NATOMS_CAP];
__device__ int    g_off[NATOMS_CAP + 1];
__device__ int    g_perm[NEDGES_CAP];

// ---- host-side stream/event objects (created once; host resources only) ----
static cudaStream_t g_s2 = nullptr;
static cudaEvent_t  g_evA = nullptr, g_evB = nullptr;

// -------------------------------------------------------------------------
// Chain A kernels: hist -> scan -> scatter(+zero)
// -------------------------------------------------------------------------
__global__ __launch_bounds__(256)
void hist_kernel(const int* __restrict__ idx_i, int n_edges) {
    int base = (blockIdx.x * 256 + threadIdx.x) * 4;
    if (base + 3 < n_edges) {
        int4 v = *reinterpret_cast<const int4*>(idx_i + base);
        atomicAdd(&g_count[v.x], 1);
        atomicAdd(&g_count[v.y], 1);
        atomicAdd(&g_count[v.z], 1);
        atomicAdd(&g_count[v.w], 1);
    } else {
        for (int k = base; k < n_edges; k++) atomicAdd(&g_count[idx_i[k]], 1);
    }
}

__global__ void scan_kernel(int n_atoms) {
    __shared__ int sh[1024];
    const int tid = threadIdx.x;
    const int per = (n_atoms + 1023) / 1024;
    const int base = tid * per;
    int s = 0;
    for (int k = 0; k < per; k++) {
        int idx = base + k;
        if (idx < n_atoms) s += g_count[idx];
    }
    sh[tid] = s;
    __syncthreads();
    for (int d = 1; d < 1024; d <<= 1) {
        int v = 0;
        if (tid >= d) v = sh[tid - d];
        __syncthreads();
        if (tid >= d) sh[tid] += v;
        __syncthreads();
    }
    int run = sh[tid] - s;
    for (int k = 0; k < per; k++) {
        int idx = base + k;
        if (idx < n_atoms) {
            int c = g_count[idx];
            g_off[idx] = run;
            g_cursor[idx] = run;
            run += c;
        }
    }
    if (tid == 1023) g_off[n_atoms] = sh[1023];
}

__global__ __launch_bounds__(256)
void util2_kernel(const int* __restrict__ idx_i, int n_edges,
                  int n_atoms, int scatter_blocks) {
    const int b = blockIdx.x;
    const int t = threadIdx.x;
    if (b < scatter_blocks) {
        int base = (b * 256 + t) * 4;
        if (base + 3 < n_edges) {
            int4 v = *reinterpret_cast<const int4*>(idx_i + base);
            int p0 = atomicAdd(&g_cursor[v.x], 1);
            int p1 = atomicAdd(&g_cursor[v.y], 1);
            int p2 = atomicAdd(&g_cursor[v.z], 1);
            int p3 = atomicAdd(&g_cursor[v.w], 1);
            g_perm[p0] = base;
            g_perm[p1] = base + 1;
            g_perm[p2] = base + 2;
            g_perm[p3] = base + 3;
        } else {
            for (int k = base; k < n_edges; k++) {
                int p = atomicAdd(&g_cursor[idx_i[k]], 1);
                g_perm[p] = k;
            }
        }
    } else {
        int i = (b - scatter_blocks) * 256 + t;
        if (i < n_atoms) g_count[i] = 0;
    }
}

// -------------------------------------------------------------------------
// Chain B kernels: mlp -> init(+mu fp16 conv)
// -------------------------------------------------------------------------
__global__ __launch_bounds__(192, 2)
void mlp_kernel(const float* __restrict__ emb,
                const float* __restrict__ W1, const float* __restrict__ b1,
                const float* __restrict__ W2, const float* __restrict__ b2,
                int n_atoms) {
    __shared__ float emb_s[AB][F];
    __shared__ float h_s[AB][F];
    const int t = threadIdx.x;

    float w2col[F];
#pragma unroll
    for (int g = 0; g < F; g++) w2col[g] = W2[g * X3F + t];

    float w1col[F];
    float bias1 = 0.f;
    if (t < F) {
#pragma unroll
        for (int f = 0; f < F; f++) w1col[f] = W1[f * F + t];
        bias1 = b1[t];
    }
    const float bias2 = b2[t];

    const int nbatch = (n_atoms + AB - 1) / AB;
    for (int batch = blockIdx.x; batch < nbatch; batch += gridDim.x) {
        const int a0 = batch * AB;
        const int lim = min(AB, n_atoms - a0);
        {
            const float4* src = reinterpret_cast<const float4*>(emb + (size_t)a0 * F);
            float4* dst = reinterpret_cast<float4*>(&emb_s[0][0]);
            const int nv = lim * F / 4;
            for (int k = t; k < nv; k += 192) dst[k] = src[k];
        }
        __syncthreads();
        if (t < F) {
            float acc[AB];
#pragma unroll
            for (int a = 0; a < AB; a++) acc[a] = bias1;
#pragma unroll
            for (int f = 0; f < F; f += 4) {
#pragma unroll
                for (int a = 0; a < AB; a++) {
                    float4 e4 = *reinterpret_cast<const float4*>(&emb_s[a][f]);
                    acc[a] = fmaf(e4.x, w1col[f], acc[a]);
                    acc[a] = fmaf(e4.y, w1col[f + 1], acc[a]);
                    acc[a] = fmaf(e4.z, w1col[f + 2], acc[a]);
                    acc[a] = fmaf(e4.w, w1col[f + 3], acc[a]);
                }
            }
#pragma unroll
            for (int a = 0; a < AB; a++) {
                float v = acc[a];
                h_s[a][t] = v / (1.0f + __expf(-v));
            }
        }
        __syncthreads();
        {
            float acc[AB];
#pragma unroll
            for (int a = 0; a < AB; a++) acc[a] = bias2;
#pragma unroll
            for (int g = 0; g < F; g += 4) {
#pragma unroll
                for (int a = 0; a < AB; a++) {
                    float4 h4 = *reinterpret_cast<const float4*>(&h_s[a][g]);
                    acc[a] = fmaf(h4.x, w2col[g], acc[a]);
                    acc[a] = fmaf(h4.y, w2col[g + 1], acc[a]);
                    acc[a] = fmaf(h4.z, w2col[g + 2], acc[a]);
                    acc[a] = fmaf(h4.w, w2col[g + 3], acc[a]);
                }
            }
            for (int a = 0; a < lim; a++)
                g_x_h[(size_t)(a0 + a) * X3F + t] = __float2half(acc[a]);
        }
        __syncthreads();
    }
}

__global__ __launch_bounds__(256)
void init_kernel(const float4* __restrict__ emb4, int nq4,
                 const float4* __restrict__ mu4, int nmu4,
                 float4* __restrict__ out4, int qinit_blocks) {
    const int b = blockIdx.x;
    const int t = threadIdx.x;
    if (b < qinit_blocks) {
        int i = b * 256 + t;
        if (i < nq4) out4[i] = emb4[i];
    } else {
        int i = (b - qinit_blocks) * 256 + t;
        if (i < nmu4) {
            float4 v = mu4[i];
            out4[nq4 + i] = v;
            __half2* xh = reinterpret_cast<__half2*>(g_mu_h);
            xh[i * 2]     = __floats2half2_rn(v.x, v.y);
            xh[i * 2 + 1] = __floats2half2_rn(v.z, v.w);
        }
    }
}

// -------------------------------------------------------------------------
// Gather: EXACT R12 configuration (4 CTAs/SM, 64 regs, measured 135.4us).
// -------------------------------------------------------------------------
__device__ __forceinline__ void red2(float* p, float2 v) {
    asm volatile("red.global.add.v2.f32 [%0], {%1,%2};"
                 :: "l"(p), "f"(v.x), "f"(v.y)
                 : "memory");
}

struct GatherData {
    uint32_t xq, xr, xm;
    uint32_t mj0, mj1, mj2;
};

__device__ __forceinline__ void load_gather(GatherData& d, int j, int c) {
    const uint32_t* xrow = reinterpret_cast<const uint32_t*>(g_x_h + (size_t)j * X3F);
    d.xq = xrow[c]; d.xr = xrow[32 + c]; d.xm = xrow[64 + c];
    const uint32_t* murow = reinterpret_cast<const uint32_t*>(g_mu_h + (size_t)j * X3F);
    d.mj0 = murow[c]; d.mj1 = murow[32 + c]; d.mj2 = murow[64 + c];
}

__device__ __forceinline__ float2 h2f2(uint32_t u) {
    return __half22float2(*reinterpret_cast<__half2*>(&u));
}

__device__ __forceinline__ void flush_atom2(int cur, int c,
                                            float2 q, float2 m0, float2 m1, float2 m2,
                                            float* q_out, float* mu_out) {
    red2(q_out + (size_t)cur * F + c * 2, q);
    float* mo = mu_out + (size_t)cur * X3F + c * 2;
    red2(mo, m0);
    red2(mo + F, m1);
    red2(mo + 2 * F, m2);
}

__global__ __launch_bounds__(256, 4)
void gather_kernel(const float* __restrict__ Wij,
                   const float* __restrict__ dir_ij,
                   const int* __restrict__ idx_i,
                   const int* __restrict__ idx_j,
                   float* __restrict__ q_out,
                   float* __restrict__ mu_out,
                   int n_edges, int n_atoms) {
    __shared__ int4   meta_i[8][CHUNK];
    __shared__ float4 meta_f[8][CHUNK];

    const int t = threadIdx.x;
    const int w = t >> 5;
    const int c = t & 31;
    const int base = (blockIdx.x * 8 + w) * CHUNK;

    {
        int p = base + c;
        int e = 0, i = PAD_ATOM, j = 0;
        float d0 = 0.f, d1 = 0.f, d2 = 0.f;
        if (p < n_edges) {
            e = g_perm[p];
            i = idx_i[e];
            j = idx_j[e];
            d0 = dir_ij[(size_t)e * 3 + 0];
            d1 = dir_ij[(size_t)e * 3 + 1];
            d2 = dir_ij[(size_t)e * 3 + 2];
        }
        meta_i[w][c] = make_int4(e, i, j, 0);
        meta_f[w][c] = make_float4(d0, d1, d2, 0.f);
    }
    __syncwarp();

    float2 q  = make_float2(0.f, 0.f);
    float2 m0 = q, m1 = q, m2 = q;
    int cur = -1;

    int4 mi = meta_i[w][0];
    GatherData d;
    load_gather(d, mi.z, c);

#pragma unroll 4
    for (int k = 0; k < CHUNK; k++) {
        int4 nmi = meta_i[w][(k + 1 < CHUNK) ? (k + 1) : (CHUNK - 1)];
        GatherData nd;
        load_gather(nd, nmi.z, c);

        const float2* wp = reinterpret_cast<const float2*>(Wij + (size_t)mi.x * X3F);
        float2 wq = __ldcs(wp + c);
        float2 wr = __ldcs(wp + 32 + c);
        float2 wm = __ldcs(wp + 64 + c);

        if (mi.y != cur) {
            if (cur >= 0 && cur < n_atoms)
                flush_atom2(cur, c, q, m0, m1, m2, q_out, mu_out);
            cur = mi.y;
            q = m0 = m1 = m2 = make_float2(0.f, 0.f);
        }
        float4 mf = meta_f[w][k];

        float2 xq = h2f2(d.xq), xr = h2f2(d.xr), xm = h2f2(d.xm);
        float2 mj0 = h2f2(d.mj0), mj1 = h2f2(d.mj1), mj2 = h2f2(d.mj2);

        q.x = fmaf(wq.x, xq.x, q.x);
        q.y = fmaf(wq.y, xq.y, q.y);

        float2 a = make_float2(wr.x * xr.x, wr.y * xr.y);
        float2 b = make_float2(wm.x * xm.x, wm.y * xm.y);

        m0.x = fmaf(a.x, mf.x, fmaf(b.x, mj0.x, m0.x));
        m0.y = fmaf(a.y, mf.x, fmaf(b.y, mj0.y, m0.y));
        m1.x = fmaf(a.x, mf.y, fmaf(b.x, mj1.x, m1.x));
        m1.y = fmaf(a.y, mf.y, fmaf(b.y, mj1.y, m1.y));
        m2.x = fmaf(a.x, mf.z, fmaf(b.x, mj2.x, m2.x));
        m2.y = fmaf(a.y, mf.z, fmaf(b.y, mj2.y, m2.y));

        d = nd;
        mi = nmi;
    }
    if (cur >= 0 && cur < n_atoms)
        flush_atom2(cur, c, q, m0, m1, m2, q_out, mu_out);
}

// -------------------------------------------------------------------------
// Launch: two concurrent chains, fork/join via events (graph-capturable).
//   chain A (main stream): hist -> scan -> scatter+zero
//   chain B (g_s2):        mlp -> init+mu conv
//   join -> gather (main stream)
// -------------------------------------------------------------------------
extern "C" void kernel_launch(void* const* d_in, const int* in_sizes, int n_in,
                              void* d_out, int out_size) {
    const float* emb   = (const float*)d_in[0];
    const float* mu    = (const float*)d_in[1];
    const float* Wij   = (const float*)d_in[2];
    const float* dir   = (const float*)d_in[3];
    const int*   idx_i = (const int*)d_in[4];
    const int*   idx_j = (const int*)d_in[5];
    const float* W1    = (const float*)d_in[6];
    const float* b1    = (const float*)d_in[7];
    const float* W2    = (const float*)d_in[8];
    const float* b2    = (const float*)d_in[9];

    const int n_atoms = in_sizes[0] / F;       // 25000
    const int n_edges = in_sizes[4];           // 800000

    float* q_out  = (float*)d_out;
    float* mu_out = (float*)d_out + (size_t)n_atoms * F;

    // one-time host resource creation (no device memory involved)
    if (g_s2 == nullptr) {
        cudaStreamCreateWithFlags(&g_s2, cudaStreamNonBlocking);
        cudaEventCreateWithFlags(&g_evA, cudaEventDisableTiming);
        cudaEventCreateWithFlags(&g_evB, cudaEventDisableTiming);
    }

    // fork: s2 joins the (possibly capturing) main stream
    cudaEventRecord(g_evA, 0);
    cudaStreamWaitEvent(g_s2, g_evA, 0);

    // ---- chain B on s2: mlp -> init ----
    mlp_kernel<<<296, 192, 0, g_s2>>>(emb, W1, b1, W2, b2, n_atoms);
    {
        int nq4  = n_atoms * F / 4;
        int nmu4 = n_atoms * X3F / 4;
        int qinit_blocks  = (nq4 + 255) / 256;
        int muinit_blocks = (nmu4 + 255) / 256;
        init_kernel<<<qinit_blocks + muinit_blocks, 256, 0, g_s2>>>(
            (const float4*)emb, nq4, (const float4*)mu, nmu4,
            (float4*)d_out, qinit_blocks);
    }

    // ---- chain A on main stream: hist -> scan -> scatter+zero ----
    hist_kernel<<<(n_edges / 4 + 255) / 256, 256>>>(idx_i, n_edges);
    scan_kernel<<<1, 1024>>>(n_atoms);
    {
        int scatter_blocks = (n_edges / 4 + 255) / 256;
        int zero_blocks = (n_atoms + 255) / 256;
        util2_kernel<<<scatter_blocks + zero_blocks, 256>>>(
            idx_i, n_edges, n_atoms, scatter_blocks);
    }

    // join: main stream waits for chain B
    cudaEventRecord(g_evB, g_s2);
    cudaStreamWaitEvent(0, g_evB, 0);

    // ---- gather (R12-proven config) ----
    {
        int edges_per_block = 8 * CHUNK;   // 8 warps x 32 edges
        int blocks = (n_edges + edges_per_block - 1) / edges_per_block;
        gather_kernel<<<blocks, 256>>>(Wij, dir, idx_i, idx_j,
                                       q_out, mu_out, n_edges, n_atoms);
    }
}

// round 16
// speedup vs baseline: 1.1129x; 1.0125x over previous
#include <cuda_runtime.h>
#include <cuda_fp16.h>
#include <cstdint>

#define F 64
#define X3F 192
#define AB 8
#define CHUNK 32
#define PAD_ATOM 0x3fffffff
#define NATOMS_CAP 25600
#define NEDGES_CAP 800000
#define SCAN_P 32   // atoms per scan thread (compile-time, register-resident)

// ---- device scratch (static: no allocs allowed) ----
__device__ __half g_x_h[(size_t)NATOMS_CAP * X3F];   // MLP output, fp16
__device__ __half g_mu_h[(size_t)NATOMS_CAP * X3F];  // mu copy, fp16
__device__ int    g_count[NATOMS_CAP];               // zeroed statically / re-zeroed each call
__device__ int    g_cursor[NATOMS_CAP];
__device__ int    g_off[NATOMS_CAP + 1];
__device__ int    g_perm[NEDGES_CAP];

// ---- host-side stream/event objects (created once; host resources only) ----
static cudaStream_t g_s2 = nullptr;
static cudaEvent_t  g_evA = nullptr, g_evB = nullptr;

// -------------------------------------------------------------------------
// Chain A kernels: hist -> scan -> scatter(+zero)
// -------------------------------------------------------------------------
__global__ __launch_bounds__(256)
void hist_kernel(const int* __restrict__ idx_i, int n_edges) {
    int base = (blockIdx.x * 256 + threadIdx.x) * 4;
    if (base + 3 < n_edges) {
        int4 v = *reinterpret_cast<const int4*>(idx_i + base);
        atomicAdd(&g_count[v.x], 1);
        atomicAdd(&g_count[v.y], 1);
        atomicAdd(&g_count[v.z], 1);
        atomicAdd(&g_count[v.w], 1);
    } else {
        for (int k = base; k < n_edges; k++) atomicAdd(&g_count[idx_i[k]], 1);
    }
}

// Single-block warp-shuffle scan. Each thread owns SCAN_P contiguous atoms,
// loaded as unrolled int4 (register-resident), 2 barriers total.
__global__ __launch_bounds__(1024)
void scan_kernel(int n_atoms) {
    const int tid = threadIdx.x;
    const int lane = tid & 31;
    const int wid = tid >> 5;
    const int base = tid * SCAN_P;

    // load SCAN_P counts as 8 unrolled int4 (batched, one L2 round trip)
    int cnt[SCAN_P];
#pragma unroll
    for (int v4 = 0; v4 < SCAN_P / 4; v4++) {
        int idx = base + v4 * 4;
        int4 v;
        if (idx + 3 < n_atoms) {
            v = *reinterpret_cast<const int4*>(&g_count[idx]);
        } else {
            v.x = (idx     < n_atoms) ? g_count[idx]     : 0;
            v.y = (idx + 1 < n_atoms) ? g_count[idx + 1] : 0;
            v.z = (idx + 2 < n_atoms) ? g_count[idx + 2] : 0;
            v.w = (idx + 3 < n_atoms) ? g_count[idx + 3] : 0;
        }
        cnt[v4 * 4 + 0] = v.x; cnt[v4 * 4 + 1] = v.y;
        cnt[v4 * 4 + 2] = v.z; cnt[v4 * 4 + 3] = v.w;
    }
    int s = 0;
#pragma unroll
    for (int k = 0; k < SCAN_P; k++) s += cnt[k];

    // warp inclusive scan of thread sums
    int incl = s;
#pragma unroll
    for (int d = 1; d < 32; d <<= 1) {
        int n = __shfl_up_sync(0xffffffffu, incl, d);
        if (lane >= d) incl += n;
    }

    __shared__ int wsum[32];
    if (lane == 31) wsum[wid] = incl;
    __syncthreads();
    if (wid == 0) {
        int wv = wsum[lane];
#pragma unroll
        for (int d = 1; d < 32; d <<= 1) {
            int n = __shfl_up_sync(0xffffffffu, wv, d);
            if (lane >= d) wv += n;
        }
        wsum[lane] = wv;
    }
    __syncthreads();

    int run = incl - s + (wid > 0 ? wsum[wid - 1] : 0);  // exclusive prefix

    // write prefixes (unrolled; counts already in registers)
#pragma unroll
    for (int k = 0; k < SCAN_P; k++) {
        int idx = base + k;
        if (idx < n_atoms) {
            g_off[idx] = run;
            g_cursor[idx] = run;
            run += cnt[k];
        }
    }
    if (tid == 1023) g_off[n_atoms] = incl + (wid > 0 ? wsum[wid - 1] : 0);
}

__global__ __launch_bounds__(256)
void util2_kernel(const int* __restrict__ idx_i, int n_edges,
                  int n_atoms, int scatter_blocks) {
    const int b = blockIdx.x;
    const int t = threadIdx.x;
    if (b < scatter_blocks) {
        int base = (b * 256 + t) * 4;
        if (base + 3 < n_edges) {
            int4 v = *reinterpret_cast<const int4*>(idx_i + base);
            int p0 = atomicAdd(&g_cursor[v.x], 1);
            int p1 = atomicAdd(&g_cursor[v.y], 1);
            int p2 = atomicAdd(&g_cursor[v.z], 1);
            int p3 = atomicAdd(&g_cursor[v.w], 1);
            g_perm[p0] = base;
            g_perm[p1] = base + 1;
            g_perm[p2] = base + 2;
            g_perm[p3] = base + 3;
        } else {
            for (int k = base; k < n_edges; k++) {
                int p = atomicAdd(&g_cursor[idx_i[k]], 1);
                g_perm[p] = k;
            }
        }
    } else {
        int i = (b - scatter_blocks) * 256 + t;
        if (i < n_atoms) g_count[i] = 0;
    }
}

// -------------------------------------------------------------------------
// Chain B kernels: mlp -> init(+mu fp16 conv)
// -------------------------------------------------------------------------
__global__ __launch_bounds__(192, 2)
void mlp_kernel(const float* __restrict__ emb,
                const float* __restrict__ W1, const float* __restrict__ b1,
                const float* __restrict__ W2, const float* __restrict__ b2,
                int n_atoms) {
    __shared__ float emb_s[AB][F];
    __shared__ float h_s[AB][F];
    const int t = threadIdx.x;

    float w2col[F];
#pragma unroll
    for (int g = 0; g < F; g++) w2col[g] = W2[g * X3F + t];

    float w1col[F];
    float bias1 = 0.f;
    if (t < F) {
#pragma unroll
        for (int f = 0; f < F; f++) w1col[f] = W1[f * F + t];
        bias1 = b1[t];
    }
    const float bias2 = b2[t];

    const int nbatch = (n_atoms + AB - 1) / AB;
    for (int batch = blockIdx.x; batch < nbatch; batch += gridDim.x) {
        const int a0 = batch * AB;
        const int lim = min(AB, n_atoms - a0);
        {
            const float4* src = reinterpret_cast<const float4*>(emb + (size_t)a0 * F);
            float4* dst = reinterpret_cast<float4*>(&emb_s[0][0]);
            const int nv = lim * F / 4;
            for (int k = t; k < nv; k += 192) dst[k] = src[k];
        }
        __syncthreads();
        if (t < F) {
            float acc[AB];
#pragma unroll
            for (int a = 0; a < AB; a++) acc[a] = bias1;
#pragma unroll
            for (int f = 0; f < F; f += 4) {
#pragma unroll
                for (int a = 0; a < AB; a++) {
                    float4 e4 = *reinterpret_cast<const float4*>(&emb_s[a][f]);
                    acc[a] = fmaf(e4.x, w1col[f], acc[a]);
                    acc[a] = fmaf(e4.y, w1col[f + 1], acc[a]);
                    acc[a] = fmaf(e4.z, w1col[f + 2], acc[a]);
                    acc[a] = fmaf(e4.w, w1col[f + 3], acc[a]);
                }
            }
#pragma unroll
            for (int a = 0; a < AB; a++) {
                float v = acc[a];
                h_s[a][t] = v / (1.0f + __expf(-v));
            }
        }
        __syncthreads();
        {
            float acc[AB];
#pragma unroll
            for (int a = 0; a < AB; a++) acc[a] = bias2;
#pragma unroll
            for (int g = 0; g < F; g += 4) {
#pragma unroll
                for (int a = 0; a < AB; a++) {
                    float4 h4 = *reinterpret_cast<const float4*>(&h_s[a][g]);
                    acc[a] = fmaf(h4.x, w2col[g], acc[a]);
                    acc[a] = fmaf(h4.y, w2col[g + 1], acc[a]);
                    acc[a] = fmaf(h4.z, w2col[g + 2], acc[a]);
                    acc[a] = fmaf(h4.w, w2col[g + 3], acc[a]);
                }
            }
            for (int a = 0; a < lim; a++)
                g_x_h[(size_t)(a0 + a) * X3F + t] = __float2half(acc[a]);
        }
        __syncthreads();
    }
}

__global__ __launch_bounds__(256)
void init_kernel(const float4* __restrict__ emb4, int nq4,
                 const float4* __restrict__ mu4, int nmu4,
                 float4* __restrict__ out4, int qinit_blocks) {
    const int b = blockIdx.x;
    const int t = threadIdx.x;
    if (b < qinit_blocks) {
        int i = b * 256 + t;
        if (i < nq4) out4[i] = emb4[i];
    } else {
        int i = (b - qinit_blocks) * 256 + t;
        if (i < nmu4) {
            float4 v = mu4[i];
            out4[nq4 + i] = v;
            __half2* xh = reinterpret_cast<__half2*>(g_mu_h);
            xh[i * 2]     = __floats2half2_rn(v.x, v.y);
            xh[i * 2 + 1] = __floats2half2_rn(v.z, v.w);
        }
    }
}

// -------------------------------------------------------------------------
// Gather: EXACT R12 configuration (4 CTAs/SM, 64 regs, measured 135.4us).
// -------------------------------------------------------------------------
__device__ __forceinline__ void red2(float* p, float2 v) {
    asm volatile("red.global.add.v2.f32 [%0], {%1,%2};"
                 :: "l"(p), "f"(v.x), "f"(v.y)
                 : "memory");
}

struct GatherData {
    uint32_t xq, xr, xm;
    uint32_t mj0, mj1, mj2;
};

__device__ __forceinline__ void load_gather(GatherData& d, int j, int c) {
    const uint32_t* xrow = reinterpret_cast<const uint32_t*>(g_x_h + (size_t)j * X3F);
    d.xq = xrow[c]; d.xr = xrow[32 + c]; d.xm = xrow[64 + c];
    const uint32_t* murow = reinterpret_cast<const uint32_t*>(g_mu_h + (size_t)j * X3F);
    d.mj0 = murow[c]; d.mj1 = murow[32 + c]; d.mj2 = murow[64 + c];
}

__device__ __forceinline__ float2 h2f2(uint32_t u) {
    return __half22float2(*reinterpret_cast<__half2*>(&u));
}

__device__ __forceinline__ void flush_atom2(int cur, int c,
                                            float2 q, float2 m0, float2 m1, float2 m2,
                                            float* q_out, float* mu_out) {
    red2(q_out + (size_t)cur * F + c * 2, q);
    float* mo = mu_out + (size_t)cur * X3F + c * 2;
    red2(mo, m0);
    red2(mo + F, m1);
    red2(mo + 2 * F, m2);
}

__global__ __launch_bounds__(256, 4)
void gather_kernel(const float* __restrict__ Wij,
                   const float* __restrict__ dir_ij,
                   const int* __restrict__ idx_i,
                   const int* __restrict__ idx_j,
                   float* __restrict__ q_out,
                   float* __restrict__ mu_out,
                   int n_edges, int n_atoms) {
    __shared__ int4   meta_i[8][CHUNK];
    __shared__ float4 meta_f[8][CHUNK];

    const int t = threadIdx.x;
    const int w = t >> 5;
    const int c = t & 31;
    const int base = (blockIdx.x * 8 + w) * CHUNK;

    {
        int p = base + c;
        int e = 0, i = PAD_ATOM, j = 0;
        float d0 = 0.f, d1 = 0.f, d2 = 0.f;
        if (p < n_edges) {
            e = g_perm[p];
            i = idx_i[e];
            j = idx_j[e];
            d0 = dir_ij[(size_t)e * 3 + 0];
            d1 = dir_ij[(size_t)e * 3 + 1];
            d2 = dir_ij[(size_t)e * 3 + 2];
        }
        meta_i[w][c] = make_int4(e, i, j, 0);
        meta_f[w][c] = make_float4(d0, d1, d2, 0.f);
    }
    __syncwarp();

    float2 q  = make_float2(0.f, 0.f);
    float2 m0 = q, m1 = q, m2 = q;
    int cur = -1;

    int4 mi = meta_i[w][0];
    GatherData d;
    load_gather(d, mi.z, c);

#pragma unroll 4
    for (int k = 0; k < CHUNK; k++) {
        int4 nmi = meta_i[w][(k + 1 < CHUNK) ? (k + 1) : (CHUNK - 1)];
        GatherData nd;
        load_gather(nd, nmi.z, c);

        const float2* wp = reinterpret_cast<const float2*>(Wij + (size_t)mi.x * X3F);
        float2 wq = __ldcs(wp + c);
        float2 wr = __ldcs(wp + 32 + c);
        float2 wm = __ldcs(wp + 64 + c);

        if (mi.y != cur) {
            if (cur >= 0 && cur < n_atoms)
                flush_atom2(cur, c, q, m0, m1, m2, q_out, mu_out);
            cur = mi.y;
            q = m0 = m1 = m2 = make_float2(0.f, 0.f);
        }
        float4 mf = meta_f[w][k];

        float2 xq = h2f2(d.xq), xr = h2f2(d.xr), xm = h2f2(d.xm);
        float2 mj0 = h2f2(d.mj0), mj1 = h2f2(d.mj1), mj2 = h2f2(d.mj2);

        q.x = fmaf(wq.x, xq.x, q.x);
        q.y = fmaf(wq.y, xq.y, q.y);

        float2 a = make_float2(wr.x * xr.x, wr.y * xr.y);
        float2 b = make_float2(wm.x * xm.x, wm.y * xm.y);

        m0.x = fmaf(a.x, mf.x, fmaf(b.x, mj0.x, m0.x));
        m0.y = fmaf(a.y, mf.x, fmaf(b.y, mj0.y, m0.y));
        m1.x = fmaf(a.x, mf.y, fmaf(b.x, mj1.x, m1.x));
        m1.y = fmaf(a.y, mf.y, fmaf(b.y, mj1.y, m1.y));
        m2.x = fmaf(a.x, mf.z, fmaf(b.x, mj2.x, m2.x));
        m2.y = fmaf(a.y, mf.z, fmaf(b.y, mj2.y, m2.y));

        d = nd;
        mi = nmi;
    }
    if (cur >= 0 && cur < n_atoms)
        flush_atom2(cur, c, q, m0, m1, m2, q_out, mu_out);
}

// -------------------------------------------------------------------------
// Launch: two concurrent chains, fork/join via events (graph-capturable).
//   chain A (main stream): hist -> scan -> scatter+zero
//   chain B (g_s2):        mlp -> init+mu conv
//   join -> gather (main stream)
// -------------------------------------------------------------------------
extern "C" void kernel_launch(void* const* d_in, const int* in_sizes, int n_in,
                              void* d_out, int out_size) {
    const float* emb   = (const float*)d_in[0];
    const float* mu    = (const float*)d_in[1];
    const float* Wij   = (const float*)d_in[2];
    const float* dir   = (const float*)d_in[3];
    const int*   idx_i = (const int*)d_in[4];
    const int*   idx_j = (const int*)d_in[5];
    const float* W1    = (const float*)d_in[6];
    const float* b1    = (const float*)d_in[7];
    const float* W2    = (const float*)d_in[8];
    const float* b2    = (const float*)d_in[9];

    const int n_atoms = in_sizes[0] / F;       // 25000
    const int n_edges = in_sizes[4];           // 800000

    float* q_out  = (float*)d_out;
    float* mu_out = (float*)d_out + (size_t)n_atoms * F;

    // one-time host resource creation (no device memory involved)
    if (g_s2 == nullptr) {
        cudaStreamCreateWithFlags(&g_s2, cudaStreamNonBlocking);
        cudaEventCreateWithFlags(&g_evA, cudaEventDisableTiming);
        cudaEventCreateWithFlags(&g_evB, cudaEventDisableTiming);
    }

    // fork: s2 joins the (possibly capturing) main stream
    cudaEventRecord(g_evA, 0);
    cudaStreamWaitEvent(g_s2, g_evA, 0);

    // ---- chain B on s2: mlp -> init ----
    mlp_kernel<<<296, 192, 0, g_s2>>>(emb, W1, b1, W2, b2, n_atoms);
    {
        int nq4  = n_atoms * F / 4;
        int nmu4 = n_atoms * X3F / 4;
        int qinit_blocks  = (nq4 + 255) / 256;
        int muinit_blocks = (nmu4 + 255) / 256;
        init_kernel<<<qinit_blocks + muinit_blocks, 256, 0, g_s2>>>(
            (const float4*)emb, nq4, (const float4*)mu, nmu4,
            (float4*)d_out, qinit_blocks);
    }

    // ---- chain A on main stream: hist -> scan -> scatter+zero ----
    hist_kernel<<<(n_edges / 4 + 255) / 256, 256>>>(idx_i, n_edges);
    scan_kernel<<<1, 1024>>>(n_atoms);
    {
        int scatter_blocks = (n_edges / 4 + 255) / 256;
        int zero_blocks = (n_atoms + 255) / 256;
        util2_kernel<<<scatter_blocks + zero_blocks, 256>>>(
            idx_i, n_edges, n_atoms, scatter_blocks);
    }

    // join: main stream waits for chain B
    cudaEventRecord(g_evB, g_s2);
    cudaStreamWaitEvent(0, g_evB, 0);

    // ---- gather (R12-proven config) ----
    {
        int edges_per_block = 8 * CHUNK;   // 8 warps x 32 edges
        int blocks = (n_edges + edges_per_block - 1) / edges_per_block;
        gather_kernel<<<blocks, 256>>>(Wij, dir, idx_i, idx_j,
                                       q_out, mu_out, n_edges, n_atoms);
    }
}

// round 17
// speedup vs baseline: 1.1974x; 1.0759x over previous
#include <cuda_runtime.h>
#include <cuda_fp16.h>
#include <cstdint>

#define F 64
#define X3F 192
#define AB 8
#define CHUNK 32
#define PAD_ATOM 0x3fffffff
#define NATOMS_CAP 25600
#define NEDGES_CAP 800000

// ---- device scratch (static: no allocs allowed) ----
__device__ __half g_x_h[(size_t)NATOMS_CAP * X3F];   // MLP output, fp16
__device__ __half g_mu_h[(size_t)NATOMS_CAP * X3F];  // mu copy, fp16
__device__ __align__(16) int g_count[NATOMS_CAP];    // zeroed statically / re-zeroed each call
__device__ __align__(16) int g_cursor[NATOMS_CAP];
__device__ __align__(16) int g_off[NATOMS_CAP + 4];
__device__ int g_perm[NEDGES_CAP];

// ---- host-side stream/event objects (created once; host resources only) ----
static cudaStream_t g_s2 = nullptr;
static cudaEvent_t  g_evA = nullptr, g_evB = nullptr;

// -------------------------------------------------------------------------
// Chain A kernels: hist -> scan -> scatter(+zero) -> init
// -------------------------------------------------------------------------
__global__ __launch_bounds__(256)
void hist_kernel(const int* __restrict__ idx_i, int n_edges) {
    int base = (blockIdx.x * 256 + threadIdx.x) * 4;
    if (base + 3 < n_edges) {
        int4 v = *reinterpret_cast<const int4*>(idx_i + base);
        atomicAdd(&g_count[v.x], 1);
        atomicAdd(&g_count[v.y], 1);
        atomicAdd(&g_count[v.z], 1);
        atomicAdd(&g_count[v.w], 1);
    } else {
        for (int k = base; k < n_edges; k++) atomicAdd(&g_count[idx_i[k]], 1);
    }
}

// Coalesced multi-pass single-block scan: each thread owns 4 CONTIGUOUS
// atoms per pass (lane-adjacent int4 -> coalesced), carry across passes,
// next pass's load prefetched before this pass's shuffle scan.
__global__ __launch_bounds__(1024)
void scan_kernel(int n_atoms) {
    const int tid = threadIdx.x;
    const int lane = tid & 31;
    const int wid = tid >> 5;
    __shared__ int wsum[2][32];

    const int npass = (n_atoms + 4095) / 4096;
    int carry = 0;

    // pass-0 load
    int4 v = make_int4(0, 0, 0, 0);
    {
        int idx = tid * 4;
        if (idx + 3 < n_atoms) v = *reinterpret_cast<const int4*>(&g_count[idx]);
        else {
            if (idx     < n_atoms) v.x = g_count[idx];
            if (idx + 1 < n_atoms) v.y = g_count[idx + 1];
            if (idx + 2 < n_atoms) v.z = g_count[idx + 2];
            if (idx + 3 < n_atoms) v.w = g_count[idx + 3];
        }
    }

    for (int p = 0; p < npass; p++) {
        // prefetch next pass (coalesced) before the scan of this pass
        int4 vn = make_int4(0, 0, 0, 0);
        if (p + 1 < npass) {
            int idx = (p + 1) * 4096 + tid * 4;
            if (idx + 3 < n_atoms) vn = *reinterpret_cast<const int4*>(&g_count[idx]);
            else {
                if (idx     < n_atoms) vn.x = g_count[idx];
                if (idx + 1 < n_atoms) vn.y = g_count[idx + 1];
                if (idx + 2 < n_atoms) vn.z = g_count[idx + 2];
                if (idx + 3 < n_atoms) vn.w = g_count[idx + 3];
            }
        }

        int s = v.x + v.y + v.z + v.w;
        int incl = s;
#pragma unroll
        for (int d = 1; d < 32; d <<= 1) {
            int n = __shfl_up_sync(0xffffffffu, incl, d);
            if (lane >= d) incl += n;
        }
        const int buf = p & 1;
        if (lane == 31) wsum[buf][wid] = incl;
        __syncthreads();
        if (wid == 0) {
            int wv = wsum[buf][lane];
#pragma unroll
            for (int d = 1; d < 32; d <<= 1) {
                int n = __shfl_up_sync(0xffffffffu, wv, d);
                if (lane >= d) wv += n;
            }
            wsum[buf][lane] = wv;
        }
        __syncthreads();

        int excl = carry + incl - s + (wid ? wsum[buf][wid - 1] : 0);
        int idx = p * 4096 + tid * 4;
        int4 off;
        off.x = excl;
        off.y = off.x + v.x;
        off.z = off.y + v.y;
        off.w = off.z + v.z;
        if (idx + 3 < n_atoms) {
            *reinterpret_cast<int4*>(&g_off[idx])    = off;
            *reinterpret_cast<int4*>(&g_cursor[idx]) = off;
        } else {
            if (idx     < n_atoms) { g_off[idx]     = off.x; g_cursor[idx]     = off.x; }
            if (idx + 1 < n_atoms) { g_off[idx + 1] = off.y; g_cursor[idx + 1] = off.y; }
            if (idx + 2 < n_atoms) { g_off[idx + 2] = off.z; g_cursor[idx + 2] = off.z; }
            if (idx + 3 < n_atoms) { g_off[idx + 3] = off.w; g_cursor[idx + 3] = off.w; }
        }
        carry += wsum[buf][31];   // block total of this pass (uniform after barrier)
        v = vn;
    }
    if (tid == 0) g_off[n_atoms] = carry;
}

__global__ __launch_bounds__(256)
void util2_kernel(const int* __restrict__ idx_i, int n_edges,
                  int n_atoms, int scatter_blocks) {
    const int b = blockIdx.x;
    const int t = threadIdx.x;
    if (b < scatter_blocks) {
        int base = (b * 256 + t) * 4;
        if (base + 3 < n_edges) {
            int4 v = *reinterpret_cast<const int4*>(idx_i + base);
            int p0 = atomicAdd(&g_cursor[v.x], 1);
            int p1 = atomicAdd(&g_cursor[v.y], 1);
            int p2 = atomicAdd(&g_cursor[v.z], 1);
            int p3 = atomicAdd(&g_cursor[v.w], 1);
            g_perm[p0] = base;
            g_perm[p1] = base + 1;
            g_perm[p2] = base + 2;
            g_perm[p3] = base + 3;
        } else {
            for (int k = base; k < n_edges; k++) {
                int p = atomicAdd(&g_cursor[idx_i[k]], 1);
                g_perm[p] = k;
            }
        }
    } else {
        int i = (b - scatter_blocks) * 256 + t;
        if (i < n_atoms) g_count[i] = 0;
    }
}

__global__ __launch_bounds__(256)
void init_kernel(const float4* __restrict__ emb4, int nq4,
                 const float4* __restrict__ mu4, int nmu4,
                 float4* __restrict__ out4, int qinit_blocks) {
    const int b = blockIdx.x;
    const int t = threadIdx.x;
    if (b < qinit_blocks) {
        int i = b * 256 + t;
        if (i < nq4) out4[i] = emb4[i];
    } else {
        int i = (b - qinit_blocks) * 256 + t;
        if (i < nmu4) {
            float4 v = mu4[i];
            out4[nq4 + i] = v;
            __half2* xh = reinterpret_cast<__half2*>(g_mu_h);
            xh[i * 2]     = __floats2half2_rn(v.x, v.y);
            xh[i * 2 + 1] = __floats2half2_rn(v.z, v.w);
        }
    }
}

// -------------------------------------------------------------------------
// Chain B kernel: mlp (alone on its stream now)
// -------------------------------------------------------------------------
__global__ __launch_bounds__(192, 2)
void mlp_kernel(const float* __restrict__ emb,
                const float* __restrict__ W1, const float* __restrict__ b1,
                const float* __restrict__ W2, const float* __restrict__ b2,
                int n_atoms) {
    __shared__ float emb_s[AB][F];
    __shared__ float h_s[AB][F];
    const int t = threadIdx.x;

    float w2col[F];
#pragma unroll
    for (int g = 0; g < F; g++) w2col[g] = W2[g * X3F + t];

    float w1col[F];
    float bias1 = 0.f;
    if (t < F) {
#pragma unroll
        for (int f = 0; f < F; f++) w1col[f] = W1[f * F + t];
        bias1 = b1[t];
    }
    const float bias2 = b2[t];

    const int nbatch = (n_atoms + AB - 1) / AB;
    for (int batch = blockIdx.x; batch < nbatch; batch += gridDim.x) {
        const int a0 = batch * AB;
        const int lim = min(AB, n_atoms - a0);
        {
            const float4* src = reinterpret_cast<const float4*>(emb + (size_t)a0 * F);
            float4* dst = reinterpret_cast<float4*>(&emb_s[0][0]);
            const int nv = lim * F / 4;
            for (int k = t; k < nv; k += 192) dst[k] = src[k];
        }
        __syncthreads();
        if (t < F) {
            float acc[AB];
#pragma unroll
            for (int a = 0; a < AB; a++) acc[a] = bias1;
#pragma unroll
            for (int f = 0; f < F; f += 4) {
#pragma unroll
                for (int a = 0; a < AB; a++) {
                    float4 e4 = *reinterpret_cast<const float4*>(&emb_s[a][f]);
                    acc[a] = fmaf(e4.x, w1col[f], acc[a]);
                    acc[a] = fmaf(e4.y, w1col[f + 1], acc[a]);
                    acc[a] = fmaf(e4.z, w1col[f + 2], acc[a]);
                    acc[a] = fmaf(e4.w, w1col[f + 3], acc[a]);
                }
            }
#pragma unroll
            for (int a = 0; a < AB; a++) {
                float v = acc[a];
                h_s[a][t] = v / (1.0f + __expf(-v));
            }
        }
        __syncthreads();
        {
            float acc[AB];
#pragma unroll
            for (int a = 0; a < AB; a++) acc[a] = bias2;
#pragma unroll
            for (int g = 0; g < F; g += 4) {
#pragma unroll
                for (int a = 0; a < AB; a++) {
                    float4 h4 = *reinterpret_cast<const float4*>(&h_s[a][g]);
                    acc[a] = fmaf(h4.x, w2col[g], acc[a]);
                    acc[a] = fmaf(h4.y, w2col[g + 1], acc[a]);
                    acc[a] = fmaf(h4.z, w2col[g + 2], acc[a]);
                    acc[a] = fmaf(h4.w, w2col[g + 3], acc[a]);
                }
            }
            for (int a = 0; a < lim; a++)
                g_x_h[(size_t)(a0 + a) * X3F + t] = __float2half(acc[a]);
        }
        __syncthreads();
    }
}

// -------------------------------------------------------------------------
// Gather: EXACT R12 configuration (4 CTAs/SM, 64 regs, measured 135.4us).
// -------------------------------------------------------------------------
__device__ __forceinline__ void red2(float* p, float2 v) {
    asm volatile("red.global.add.v2.f32 [%0], {%1,%2};"
                 :: "l"(p), "f"(v.x), "f"(v.y)
                 : "memory");
}

struct GatherData {
    uint32_t xq, xr, xm;
    uint32_t mj0, mj1, mj2;
};

__device__ __forceinline__ void load_gather(GatherData& d, int j, int c) {
    const uint32_t* xrow = reinterpret_cast<const uint32_t*>(g_x_h + (size_t)j * X3F);
    d.xq = xrow[c]; d.xr = xrow[32 + c]; d.xm = xrow[64 + c];
    const uint32_t* murow = reinterpret_cast<const uint32_t*>(g_mu_h + (size_t)j * X3F);
    d.mj0 = murow[c]; d.mj1 = murow[32 + c]; d.mj2 = murow[64 + c];
}

__device__ __forceinline__ float2 h2f2(uint32_t u) {
    return __half22float2(*reinterpret_cast<__half2*>(&u));
}

__device__ __forceinline__ void flush_atom2(int cur, int c,
                                            float2 q, float2 m0, float2 m1, float2 m2,
                                            float* q_out, float* mu_out) {
    red2(q_out + (size_t)cur * F + c * 2, q);
    float* mo = mu_out + (size_t)cur * X3F + c * 2;
    red2(mo, m0);
    red2(mo + F, m1);
    red2(mo + 2 * F, m2);
}

__global__ __launch_bounds__(256, 4)
void gather_kernel(const float* __restrict__ Wij,
                   const float* __restrict__ dir_ij,
                   const int* __restrict__ idx_i,
                   const int* __restrict__ idx_j,
                   float* __restrict__ q_out,
                   float* __restrict__ mu_out,
                   int n_edges, int n_atoms) {
    __shared__ int4   meta_i[8][CHUNK];
    __shared__ float4 meta_f[8][CHUNK];

    const int t = threadIdx.x;
    const int w = t >> 5;
    const int c = t & 31;
    const int base = (blockIdx.x * 8 + w) * CHUNK;

    {
        int p = base + c;
        int e = 0, i = PAD_ATOM, j = 0;
        float d0 = 0.f, d1 = 0.f, d2 = 0.f;
        if (p < n_edges) {
            e = g_perm[p];
            i = idx_i[e];
            j = idx_j[e];
            d0 = dir_ij[(size_t)e * 3 + 0];
            d1 = dir_ij[(size_t)e * 3 + 1];
            d2 = dir_ij[(size_t)e * 3 + 2];
        }
        meta_i[w][c] = make_int4(e, i, j, 0);
        meta_f[w][c] = make_float4(d0, d1, d2, 0.f);
    }
    __syncwarp();

    float2 q  = make_float2(0.f, 0.f);
    float2 m0 = q, m1 = q, m2 = q;
    int cur = -1;

    int4 mi = meta_i[w][0];
    GatherData d;
    load_gather(d, mi.z, c);

#pragma unroll 4
    for (int k = 0; k < CHUNK; k++) {
        int4 nmi = meta_i[w][(k + 1 < CHUNK) ? (k + 1) : (CHUNK - 1)];
        GatherData nd;
        load_gather(nd, nmi.z, c);

        const float2* wp = reinterpret_cast<const float2*>(Wij + (size_t)mi.x * X3F);
        float2 wq = __ldcs(wp + c);
        float2 wr = __ldcs(wp + 32 + c);
        float2 wm = __ldcs(wp + 64 + c);

        if (mi.y != cur) {
            if (cur >= 0 && cur < n_atoms)
                flush_atom2(cur, c, q, m0, m1, m2, q_out, mu_out);
            cur = mi.y;
            q = m0 = m1 = m2 = make_float2(0.f, 0.f);
        }
        float4 mf = meta_f[w][k];

        float2 xq = h2f2(d.xq), xr = h2f2(d.xr), xm = h2f2(d.xm);
        float2 mj0 = h2f2(d.mj0), mj1 = h2f2(d.mj1), mj2 = h2f2(d.mj2);

        q.x = fmaf(wq.x, xq.x, q.x);
        q.y = fmaf(wq.y, xq.y, q.y);

        float2 a = make_float2(wr.x * xr.x, wr.y * xr.y);
        float2 b = make_float2(wm.x * xm.x, wm.y * xm.y);

        m0.x = fmaf(a.x, mf.x, fmaf(b.x, mj0.x, m0.x));
        m0.y = fmaf(a.y, mf.x, fmaf(b.y, mj0.y, m0.y));
        m1.x = fmaf(a.x, mf.y, fmaf(b.x, mj1.x, m1.x));
        m1.y = fmaf(a.y, mf.y, fmaf(b.y, mj1.y, m1.y));
        m2.x = fmaf(a.x, mf.z, fmaf(b.x, mj2.x, m2.x));
        m2.y = fmaf(a.y, mf.z, fmaf(b.y, mj2.y, m2.y));

        d = nd;
        mi = nmi;
    }
    if (cur >= 0 && cur < n_atoms)
        flush_atom2(cur, c, q, m0, m1, m2, q_out, mu_out);
}

// -------------------------------------------------------------------------
// Launch: two concurrent chains, fork/join via events (graph-capturable).
//   chain A (main stream): hist -> scan -> scatter+zero -> init
//   chain B (g_s2):        mlp
//   join -> gather (main stream)
// -------------------------------------------------------------------------
extern "C" void kernel_launch(void* const* d_in, const int* in_sizes, int n_in,
                              void* d_out, int out_size) {
    const float* emb   = (const float*)d_in[0];
    const float* mu    = (const float*)d_in[1];
    const float* Wij   = (const float*)d_in[2];
    const float* dir   = (const float*)d_in[3];
    const int*   idx_i = (const int*)d_in[4];
    const int*   idx_j = (const int*)d_in[5];
    const float* W1    = (const float*)d_in[6];
    const float* b1    = (const float*)d_in[7];
    const float* W2    = (const float*)d_in[8];
    const float* b2    = (const float*)d_in[9];

    const int n_atoms = in_sizes[0] / F;       // 25000
    const int n_edges = in_sizes[4];           // 800000

    float* q_out  = (float*)d_out;
    float* mu_out = (float*)d_out + (size_t)n_atoms * F;

    // one-time host resource creation (no device memory involved)
    if (g_s2 == nullptr) {
        cudaStreamCreateWithFlags(&g_s2, cudaStreamNonBlocking);
        cudaEventCreateWithFlags(&g_evA, cudaEventDisableTiming);
        cudaEventCreateWithFlags(&g_evB, cudaEventDisableTiming);
    }

    // fork: s2 joins the (possibly capturing) main stream
    cudaEventRecord(g_evA, 0);
    cudaStreamWaitEvent(g_s2, g_evA, 0);

    // ---- chain B on s2: mlp only ----
    mlp_kernel<<<296, 192, 0, g_s2>>>(emb, W1, b1, W2, b2, n_atoms);

    // ---- chain A on main stream: hist -> scan -> scatter+zero -> init ----
    hist_kernel<<<(n_edges / 4 + 255) / 256, 256>>>(idx_i, n_edges);
    scan_kernel<<<1, 1024>>>(n_atoms);
    {
        int scatter_blocks = (n_edges / 4 + 255) / 256;
        int zero_blocks = (n_atoms + 255) / 256;
        util2_kernel<<<scatter_blocks + zero_blocks, 256>>>(
            idx_i, n_edges, n_atoms, scatter_blocks);
    }
    {
        int nq4  = n_atoms * F / 4;
        int nmu4 = n_atoms * X3F / 4;
        int qinit_blocks  = (nq4 + 255) / 256;
        int muinit_blocks = (nmu4 + 255) / 256;
        init_kernel<<<qinit_blocks + muinit_blocks, 256>>>(
            (const float4*)emb, nq4, (const float4*)mu, nmu4,
            (float4*)d_out, qinit_blocks);
    }

    // join: main stream waits for chain B
    cudaEventRecord(g_evB, g_s2);
    cudaStreamWaitEvent(0, g_evB, 0);

    // ---- gather (R12-proven config) ----
    {
        int edges_per_block = 8 * CHUNK;   // 8 warps x 32 edges
        int blocks = (n_edges + edges_per_block - 1) / edges_per_block;
        gather_kernel<<<blocks, 256>>>(Wij, dir, idx_i, idx_j,
                                       q_out, mu_out, n_edges, n_atoms);
    }
}